// round 13
// baseline (speedup 1.0000x reference)
#include <cuda_runtime.h>
#include <cuda_fp16.h>
#include <math.h>

// Problem constants (fixed by the dataset)
#define Bsz 1024
#define Tn  200
#define LXn 190
#define LYn 50
#define Hd  256
#define XDd 64
#define YDd 64

#define GRID 128
#define NTHR 512
#define ROWS 8

typedef unsigned long long ull;

// ---------------- device scratch ---------------------------------------------
__device__ float g_ybT[(size_t)LYn*GRID*Hd*ROWS];   // saved new_y: [q][cta][col][8]
__device__ float g_dt[Tn];
__device__ int   g_obs[Tn];
__device__ int   g_qm [Tn];

// fp16 weight copies (converted once by conv_kernel). 16B-aligned for uint2 loads.
__device__ __align__(16) unsigned short c_fw1 [65536];
__device__ __align__(16) unsigned short c_fw2 [65536];
__device__ __align__(16) unsigned short c_ugw1[147456];
__device__ __align__(16) unsigned short c_ugw2[65536];
__device__ __align__(16) unsigned short c_rgw1[147456];
__device__ __align__(16) unsigned short c_rgw2[65536];
__device__ __align__(16) unsigned short c_nsw1[147456];
__device__ __align__(16) unsigned short c_nsw2[131072];
__device__ __align__(16) unsigned short c_ow1 [65536];

// ---------------- packed f32x2 helpers ---------------------------------------
__device__ __forceinline__ ull fma2(ull a, ull b, ull c) {
    ull d;
    asm("fma.rn.f32x2 %0, %1, %2, %3;" : "=l"(d) : "l"(a), "l"(b), "l"(c));
    return d;
}
__device__ __forceinline__ ull dup2(float x) {
    ull d;
    asm("mov.b64 %0, {%1, %1};" : "=l"(d) : "f"(x));
    return d;
}
__device__ __forceinline__ void unpk(ull u, float& lo, float& hi) {
    asm("mov.b64 {%0, %1}, %2;" : "=f"(lo), "=f"(hi) : "l"(u));
}

__device__ __forceinline__ float sigm(float x) {
    return __fdividef(1.0f, 1.0f + __expf(-x));
}
__device__ __forceinline__ float tanh_f(float x) {
    return fmaf(2.0f, sigm(2.0f*x), -1.0f);   // |err| ~1e-6 << 1e-3 budget
}

// fp16 halves of a packed u32 -> fp32 (single F2F.F32.F16 with half-select each)
__device__ __forceinline__ float lo_h(unsigned u) {
    return __half2float(__ushort_as_half((unsigned short)(u & 0xFFFFu)));
}
__device__ __forceinline__ float hi_h(unsigned u) {
    return __half2float(__ushort_as_half((unsigned short)(u >> 16)));
}

// ---------------- GEMM core (fp16 weights) ------------------------------------
// A operand in smem, layout [k][8 rows] (stride 8 floats), broadcast LDS.
// Thread computes 2 strips x 4 cols x 8 rows over k in [k0, k0+Kh), Kh % 4 == 0.
// acc[strip*16 + c*4 + rp] packs rows (2rp, 2rp+1) of column c.
// Weights: 4 fp16 per strip per k = one LDG.64 (uint2), converted in-register.

__device__ __forceinline__ void ldw4(uint2 wa[4], uint2 wb[4],
                                     const unsigned short* __restrict__ WA,
                                     const unsigned short* __restrict__ WB,
                                     int ldwA, int ldwB, int k)
{
#pragma unroll
    for (int p = 0; p < 4; p++) {
        wa[p] = __ldg((const uint2*)(WA + (size_t)(k + p)*ldwA));
        wb[p] = __ldg((const uint2*)(WB + (size_t)(k + p)*ldwB));
    }
}

template<bool DUAL>
__device__ __forceinline__ void blk4(const float* AsA, const float* AsB, int kb,
                                     const uint2 wa[4], const uint2 wb[4],
                                     ull acc[32])
{
#pragma unroll
    for (int kk = 0; kk < 4; kk++) {
        const float* ap = AsA + (kb + kk)*8;
        ulonglong2 A0 = *(const ulonglong2*)ap;
        ulonglong2 A1 = *(const ulonglong2*)(ap + 4);
        ulonglong2 B0 = A0, B1 = A1;
        if (DUAL) {
            const float* bp = AsB + (kb + kk)*8;
            B0 = *(const ulonglong2*)bp;
            B1 = *(const ulonglong2*)(bp + 4);
        }
        ull w;
        // strip A
        w = dup2(lo_h(wa[kk].x));
        acc[0]  = fma2(A0.x, w, acc[0]);  acc[1]  = fma2(A0.y, w, acc[1]);
        acc[2]  = fma2(A1.x, w, acc[2]);  acc[3]  = fma2(A1.y, w, acc[3]);
        w = dup2(hi_h(wa[kk].x));
        acc[4]  = fma2(A0.x, w, acc[4]);  acc[5]  = fma2(A0.y, w, acc[5]);
        acc[6]  = fma2(A1.x, w, acc[6]);  acc[7]  = fma2(A1.y, w, acc[7]);
        w = dup2(lo_h(wa[kk].y));
        acc[8]  = fma2(A0.x, w, acc[8]);  acc[9]  = fma2(A0.y, w, acc[9]);
        acc[10] = fma2(A1.x, w, acc[10]); acc[11] = fma2(A1.y, w, acc[11]);
        w = dup2(hi_h(wa[kk].y));
        acc[12] = fma2(A0.x, w, acc[12]); acc[13] = fma2(A0.y, w, acc[13]);
        acc[14] = fma2(A1.x, w, acc[14]); acc[15] = fma2(A1.y, w, acc[15]);
        // strip B
        w = dup2(lo_h(wb[kk].x));
        acc[16] = fma2(B0.x, w, acc[16]); acc[17] = fma2(B0.y, w, acc[17]);
        acc[18] = fma2(B1.x, w, acc[18]); acc[19] = fma2(B1.y, w, acc[19]);
        w = dup2(hi_h(wb[kk].x));
        acc[20] = fma2(B0.x, w, acc[20]); acc[21] = fma2(B0.y, w, acc[21]);
        acc[22] = fma2(B1.x, w, acc[22]); acc[23] = fma2(B1.y, w, acc[23]);
        w = dup2(lo_h(wb[kk].y));
        acc[24] = fma2(B0.x, w, acc[24]); acc[25] = fma2(B0.y, w, acc[25]);
        acc[26] = fma2(B1.x, w, acc[26]); acc[27] = fma2(B1.y, w, acc[27]);
        w = dup2(hi_h(wb[kk].y));
        acc[28] = fma2(B0.x, w, acc[28]); acc[29] = fma2(B0.y, w, acc[29]);
        acc[30] = fma2(B1.x, w, acc[30]); acc[31] = fma2(B1.y, w, acc[31]);
    }
}

template<bool DUAL>
__device__ __forceinline__ void gemm8(const float* AsA, const float* AsB,
                                      int k0, int Kh,
                                      const unsigned short* __restrict__ WA, int ldwA,
                                      const unsigned short* __restrict__ WB, int ldwB,
                                      ull acc[32])
{
#pragma unroll
    for (int i = 0; i < 32; i++) acc[i] = 0ULL;

    const int kend = k0 + Kh;
    uint2 wa0[4], wb0[4], wa1[4], wb1[4];
    ldw4(wa0, wb0, WA, WB, ldwA, ldwB, k0);

    int kb = k0;
    while (kb + 8 <= kend) {
        ldw4(wa1, wb1, WA, WB, ldwA, ldwB, kb + 4);
        blk4<DUAL>(AsA, AsB, kb, wa0, wb0, acc);
        if (kb + 8 < kend) ldw4(wa0, wb0, WA, WB, ldwA, ldwB, kb + 8);
        blk4<DUAL>(AsA, AsB, kb + 4, wa1, wb1, acc);
        kb += 8;
    }
    if (kb < kend)    // tail block of 4 (Kh % 8 == 4, e.g. Kh = 36)
        blk4<DUAL>(AsA, AsB, kb, wa0, wb0, acc);
}

// Store partials row-major: sP[base + r*rowStride + col]; lane-contiguous STS.128.
__device__ __forceinline__ void stp8(float* sP, int rowStride, int base,
                                     int cA, int cB, const ull acc[32])
{
#pragma unroll
    for (int rp = 0; rp < 4; rp++) {
        float4 rA0, rA1, rB0, rB1;
        unpk(acc[0*4 + rp],  rA0.x, rA1.x);
        unpk(acc[1*4 + rp],  rA0.y, rA1.y);
        unpk(acc[2*4 + rp],  rA0.z, rA1.z);
        unpk(acc[3*4 + rp],  rA0.w, rA1.w);
        unpk(acc[16 + 0*4 + rp], rB0.x, rB1.x);
        unpk(acc[16 + 1*4 + rp], rB0.y, rB1.y);
        unpk(acc[16 + 2*4 + rp], rB0.z, rB1.z);
        unpk(acc[16 + 3*4 + rp], rB0.w, rB1.w);
        *(float4*)(sP + base + (2*rp)*rowStride + cA)     = rA0;
        *(float4*)(sP + base + (2*rp + 1)*rowStride + cA) = rA1;
        *(float4*)(sP + base + (2*rp)*rowStride + cB)     = rB0;
        *(float4*)(sP + base + (2*rp + 1)*rowStride + cB) = rB1;
    }
}

// Sum nsplit partials for 4 rows (rh*4..rh*4+3) of column col.
template<int NSPLIT>
__device__ __forceinline__ void rde(const float* sP, int rowStride,
                                    int col, int rh, float v[4])
{
    v[0] = v[1] = v[2] = v[3] = 0.0f;
#pragma unroll
    for (int ks = 0; ks < NSPLIT; ks++) {
        const float* p = sP + ks*8*rowStride + rh*4*rowStride + col;
        v[0] += p[0];
        v[1] += p[rowStride];
        v[2] += p[2*rowStride];
        v[3] += p[3*rowStride];
    }
}

// single-column full-K core (tiny O2 stage only; fp32 weights)
__device__ __forceinline__ void gemm1f(const float* As, int K,
                                       const float* __restrict__ Wc, int ldw,
                                       float v[8])
{
    ull a0 = 0, a1 = 0, a2 = 0, a3 = 0;
    for (int k = 0; k < K; k++) {
        const float* ap = As + k*8;
        ulonglong2 A0 = *(const ulonglong2*)ap;
        ulonglong2 A1 = *(const ulonglong2*)(ap + 4);
        ull wb = dup2(__ldg(Wc + (size_t)k*ldw));
        a0 = fma2(A0.x, wb, a0); a1 = fma2(A0.y, wb, a1);
        a2 = fma2(A1.x, wb, a2); a3 = fma2(A1.y, wb, a3);
    }
    unpk(a0, v[0], v[1]); unpk(a1, v[2], v[3]);
    unpk(a2, v[4], v[5]); unpk(a3, v[6], v[7]);
}

// ---------------- init: dt / obs-slot / query maps ---------------------------
__global__ void init_kernel(const float* __restrict__ x_time,
                            const int* __restrict__ x_idx,
                            const int* __restrict__ y_idx) {
    int tid = threadIdx.x;
    for (int t = tid; t < Tn; t += blockDim.x) { g_obs[t] = -1; g_qm[t] = -1; }
    __syncthreads();
    for (int i = tid; i < LXn; i += blockDim.x) g_obs[x_idx[i]] = i;
    for (int j = tid; j < LYn; j += blockDim.x) g_qm[y_idx[j]] = j;
    __syncthreads();
    for (int t = tid; t < Tn; t += blockDim.x) {
        float d;
        float tlast = x_time[Tn - 1];
        if (t == 0)      d = tlast - (tlast + 0.01f);
        else if (t == 1) d = tlast - x_time[0];
        else             d = x_time[t - 2] - x_time[t - 1];
        g_dt[t] = d;
    }
}

// ---------------- conv: fp32 weights -> fp16 copies ---------------------------
__device__ __forceinline__ unsigned short hfq(float x) {
    __half h = __float2half_rn(x);
    return *reinterpret_cast<unsigned short*>(&h);
}

__global__ void conv_kernel(const float* __restrict__ fw1, const float* __restrict__ fw2,
                            const float* __restrict__ ugw1, const float* __restrict__ ugw2,
                            const float* __restrict__ rgw1, const float* __restrict__ rgw2,
                            const float* __restrict__ nsw1, const float* __restrict__ nsw2,
                            const float* __restrict__ ow1) {
    int i  = blockIdx.x*blockDim.x + threadIdx.x;
    int st = gridDim.x*blockDim.x;
    for (int k = i; k < 147456; k += st) {
        if (k < 65536) {
            c_fw1[k]  = hfq(fw1[k]);
            c_fw2[k]  = hfq(fw2[k]);
            c_ugw2[k] = hfq(ugw2[k]);
            c_rgw2[k] = hfq(rgw2[k]);
            c_ow1[k]  = hfq(ow1[k]);
        }
        if (k < 131072) c_nsw2[k] = hfq(nsw2[k]);
        c_ugw1[k] = hfq(ugw1[k]);
        c_rgw1[k] = hfq(rgw1[k]);
        c_nsw1[k] = hfq(nsw1[k]);
    }
}

// ---------------- smem layout (floats) ----------------------------------------
#define OFF_A  0        // [576][8] cat(hi, s, x)
#define OFF_C  4608     // [576][8] cat(c1, c2, x)
#define OFF_H  9216     // [256][8]
#define OFF_S  11264    // [256][8]
#define OFF_TF 13312    // [256][8]
#define OFF_TU 15360    // [256][8]
#define OFF_TR 17408    // [256][8]
#define OFF_TN 19456    // [256][8]
#define OFF_U  21504    // [256][8]
#define OFF_P  23552    // partials: up to 16 slices x 8 rows x 256 cols (row-major)
#define SMEM_FLOATS 56320   // 225,280 bytes

// ---------------- persistent per-CTA recurrence -------------------------------
__global__ void __launch_bounds__(NTHR, 1)
recur_kernel(const float* __restrict__ xd, const float* __restrict__ xm,
             const float* __restrict__ ug_b1, const float* __restrict__ ug_b2,
             const float* __restrict__ rg_b1, const float* __restrict__ rg_b2,
             const float* __restrict__ ns_b1, const float* __restrict__ ns_b2,
             const float* __restrict__ out_b1, const float* __restrict__ out_w2,
             const float* __restrict__ out_b2,
             const float* __restrict__ f_b1, const float* __restrict__ f_b2,
             float* __restrict__ out)
{
    extern __shared__ float sm[];
    float* sA  = sm + OFF_A;
    float* sC  = sm + OFF_C;
    float* sH  = sm + OFF_H;
    float* sS  = sm + OFF_S;
    float* sTF = sm + OFF_TF;
    float* sTU = sm + OFF_TU;
    float* sTR = sm + OFF_TR;
    float* sTN = sm + OFF_TN;
    float* sU  = sm + OFF_U;
    float* sP  = sm + OFF_P;

    const int tid = threadIdx.x;
    const int cta = blockIdx.x;
    const int m0  = cta * ROWS;

    // N=256 stage mapping: lane 0..31 covers 256 cols in 2 strips, 16 k-slices
    const int kq16 = tid >> 5;
    const int cAn  = (tid & 31) * 4;
    const int cBn  = 128 + cAn;
    // N=512 stage mapping: 64 col-threads x 2 strips, 8 k-slices
    const int kq8  = tid >> 6;
    const int cA6  = (tid & 63) * 4;
    // epilogue mapping
    const int ecol = tid & 255;
    const int erh  = tid >> 8;       // 0/1 -> rows 0-3 / 4-7

    for (int i = tid; i < 2048; i += NTHR) { sH[i] = 0.0f; sS[i] = 0.0f; }
    __syncthreads();

    ull acc[32];
    float v[4];

    for (int t = 0; t < Tn; t++) {
        const int   obs = g_obs[t];
        const int   q   = g_qm[t];
        const float dt  = g_dt[t];

        // ---- step prologue: s -> sA[256:512]; x -> sA/sC[512:576] ----
        if (tid < 256) {
            float4 s0 = *(float4*)&sS[tid*8];
            float4 s1 = *(float4*)&sS[tid*8 + 4];
            *(float4*)&sA[(256 + tid)*8]     = s0;
            *(float4*)&sA[(256 + tid)*8 + 4] = s1;
        }
        if (tid < XDd) {
            float xv[8];
            if (obs >= 0) {
#pragma unroll
                for (int r = 0; r < 8; r++) {
                    int off = ((m0 + r)*LXn + obs)*XDd + tid;
                    xv[r] = __ldg(xd + off) * __ldg(xm + off);
                }
            } else {
#pragma unroll
                for (int r = 0; r < 8; r++) xv[r] = 0.0f;
            }
            *(float4*)&sA[(512 + tid)*8]     = make_float4(xv[0], xv[1], xv[2], xv[3]);
            *(float4*)&sA[(512 + tid)*8 + 4] = make_float4(xv[4], xv[5], xv[6], xv[7]);
            *(float4*)&sC[(512 + tid)*8]     = make_float4(xv[0], xv[1], xv[2], xv[3]);
            *(float4*)&sC[(512 + tid)*8 + 4] = make_float4(xv[4], xv[5], xv[6], xv[7]);
        }
        // (first consumer of these regions is S3/S5 — syncs in between)

        // ---- S1: tf = tanh(h @ f_w1 + b1)  [N=256, K=256, 16 slices x 16] ----
        gemm8<false>(sH, sH, kq16*16, 16, c_fw1 + cAn, Hd, c_fw1 + cBn, Hd, acc);
        stp8(sP, 256, kq16*2048, cAn, cBn, acc);
        __syncthreads();
        {
            rde<16>(sP, 256, ecol, erh, v);
            float b = __ldg(f_b1 + ecol);
            float4 o = make_float4(tanh_f(v[0]+b), tanh_f(v[1]+b),
                                   tanh_f(v[2]+b), tanh_f(v[3]+b));
            *(float4*)(sTF + ecol*8 + erh*4) = o;
        }
        __syncthreads();

        // ---- S2: hi = h + dt*(tf @ f_w2 + b2) -> sA[0:256] ----
        gemm8<false>(sTF, sTF, kq16*16, 16, c_fw2 + cAn, Hd, c_fw2 + cBn, Hd, acc);
        stp8(sP, 256, kq16*2048, cAn, cBn, acc);
        __syncthreads();
        {
            rde<16>(sP, 256, ecol, erh, v);
            float b = __ldg(f_b2 + ecol);
            float4 h = *(float4*)(sH + ecol*8 + erh*4);
            float4 o = make_float4(h.x + dt*(v[0]+b), h.y + dt*(v[1]+b),
                                   h.z + dt*(v[2]+b), h.w + dt*(v[3]+b));
            *(float4*)(sA + ecol*8 + erh*4) = o;
        }
        __syncthreads();

        // ---- S3: N=512 (tu | tr), K=576, 8 slices x 72 ----
        gemm8<false>(sA, sA, kq8*72, 72, c_ugw1 + cA6, Hd, c_rgw1 + cA6, Hd, acc);
        stp8(sP, 512, kq8*4096, cA6, 256 + cA6, acc);
        __syncthreads();
        {
            float vu[4], vr[4];
            rde<8>(sP, 512, ecol, erh, vu);
            rde<8>(sP, 512, ecol + 256, erh, vr);
            float bu = __ldg(ug_b1 + ecol), br = __ldg(rg_b1 + ecol);
            *(float4*)(sTU + ecol*8 + erh*4) =
                make_float4(tanh_f(vu[0]+bu), tanh_f(vu[1]+bu),
                            tanh_f(vu[2]+bu), tanh_f(vu[3]+bu));
            *(float4*)(sTR + ecol*8 + erh*4) =
                make_float4(tanh_f(vr[0]+br), tanh_f(vr[1]+br),
                            tanh_f(vr[2]+br), tanh_f(vr[3]+br));
        }
        __syncthreads();

        // ---- S4: fused u/r outer layers (dual-A N=512), K=256, 8 x 32 ----
        gemm8<true>(sTU, sTR, kq8*32, 32, c_ugw2 + cA6, Hd, c_rgw2 + cA6, Hd, acc);
        stp8(sP, 512, kq8*4096, cA6, 256 + cA6, acc);
        __syncthreads();
        {
            float vu[4], vr[4];
            rde<8>(sP, 512, ecol, erh, vu);
            rde<8>(sP, 512, ecol + 256, erh, vr);
            float bu = __ldg(ug_b2 + ecol), br = __ldg(rg_b2 + ecol);
            float4 hi = *(float4*)(sA + ecol*8 + erh*4);
            float4 so = *(float4*)(sA + (256 + ecol)*8 + erh*4);
            float4 uu, c1, c2;
            uu.x = sigm(vu[0]+bu); uu.y = sigm(vu[1]+bu);
            uu.z = sigm(vu[2]+bu); uu.w = sigm(vu[3]+bu);
            float r0 = sigm(vr[0]+br), r1 = sigm(vr[1]+br);
            float r2 = sigm(vr[2]+br), r3 = sigm(vr[3]+br);
            c1 = make_float4(hi.x*r0, hi.y*r1, hi.z*r2, hi.w*r3);
            c2 = make_float4(so.x*r0, so.y*r1, so.z*r2, so.w*r3);
            *(float4*)(sU + ecol*8 + erh*4) = uu;
            *(float4*)(sC + ecol*8 + erh*4) = c1;
            *(float4*)(sC + (256 + ecol)*8 + erh*4) = c2;
        }
        __syncthreads();

        // ---- S5: tn = tanh(cc @ ns_w1 + b); N=256, K=576, 16 x 36 ----
        gemm8<false>(sC, sC, kq16*36, 36, c_nsw1 + cAn, Hd, c_nsw1 + cBn, Hd, acc);
        stp8(sP, 256, kq16*2048, cAn, cBn, acc);
        __syncthreads();
        {
            rde<16>(sP, 256, ecol, erh, v);
            float b = __ldg(ns_b1 + ecol);
            *(float4*)(sTN + ecol*8 + erh*4) =
                make_float4(tanh_f(v[0]+b), tanh_f(v[1]+b),
                            tanh_f(v[2]+b), tanh_f(v[3]+b));
        }
        __syncthreads();

        // ---- S6: ns|std (N=512, ldw=512), K=256, 8 x 32; gated update ----
        gemm8<false>(sTN, sTN, kq8*32, 32, c_nsw2 + cA6, 2*Hd, c_nsw2 + 256 + cA6, 2*Hd, acc);
        stp8(sP, 512, kq8*4096, cA6, 256 + cA6, acc);
        __syncthreads();
        {
            float vn[4], vs[4];
            rde<8>(sP, 512, ecol, erh, vn);
            rde<8>(sP, 512, ecol + 256, erh, vs);
            float b1_ = __ldg(ns_b2 + ecol), b2_ = __ldg(ns_b2 + ecol + Hd);
            float4 uu = *(float4*)(sU + ecol*8 + erh*4);
            float4 hi = *(float4*)(sA + ecol*8 + erh*4);
            float4 so = *(float4*)(sA + (256 + ecol)*8 + erh*4);
            float4 hy, sy;
            {
                float ns0 = vn[0]+b1_, sd0 = fabsf(vs[0]+b2_);
                float ns1 = vn[1]+b1_, sd1 = fabsf(vs[1]+b2_);
                float ns2 = vn[2]+b1_, sd2 = fabsf(vs[2]+b2_);
                float ns3 = vn[3]+b1_, sd3 = fabsf(vs[3]+b2_);
                hy = make_float4((1.0f-uu.x)*ns0 + uu.x*hi.x,
                                 (1.0f-uu.y)*ns1 + uu.y*hi.y,
                                 (1.0f-uu.z)*ns2 + uu.z*hi.z,
                                 (1.0f-uu.w)*ns3 + uu.w*hi.w);
                sy = make_float4(fabsf((1.0f-uu.x)*sd0 + uu.x*so.x),
                                 fabsf((1.0f-uu.y)*sd1 + uu.y*so.y),
                                 fabsf((1.0f-uu.z)*sd2 + uu.z*so.z),
                                 fabsf((1.0f-uu.w)*sd3 + uu.w*so.w));
            }
            *(float4*)(sH + ecol*8 + erh*4) = hy;
            *(float4*)(sS + ecol*8 + erh*4) = sy;
            if (q >= 0) {
                float* d = g_ybT + (((size_t)q*GRID + cta)*Hd + ecol)*8 + erh*4;
                *(float4*)d = hy;
            }
        }
        __syncthreads();
    }

    // ---- deferred out-MLP: per-CTA, 50 query states ----
    for (int q = 0; q < LYn; q++) {
        const float4* src = (const float4*)(g_ybT + ((size_t)q*GRID + cta)*Hd*8);
        float4* dstA = (float4*)sA;
        for (int i = tid; i < 512; i += NTHR) dstA[i] = src[i];
        __syncthreads();

        gemm8<false>(sA, sA, kq16*16, 16, c_ow1 + cAn, Hd, c_ow1 + cBn, Hd, acc);
        stp8(sP, 256, kq16*2048, cAn, cBn, acc);
        __syncthreads();
        {
            rde<16>(sP, 256, ecol, erh, v);
            float b = __ldg(out_b1 + ecol);
            *(float4*)(sTF + ecol*8 + erh*4) =
                make_float4(tanh_f(v[0]+b), tanh_f(v[1]+b),
                            tanh_f(v[2]+b), tanh_f(v[3]+b));
        }
        __syncthreads();

        if (tid < YDd) {
            float o[8];
            gemm1f(sTF, 256, out_w2 + tid, YDd, o);
            float b = __ldg(out_b2 + tid);
#pragma unroll
            for (int r = 0; r < 8; r++)
                out[((size_t)(m0 + r)*LYn + q)*YDd + tid] = o[r] + b;
        }
        __syncthreads();
    }
}

// ---------------- launch ------------------------------------------------------
extern "C" void kernel_launch(void* const* d_in, const int* in_sizes, int n_in,
                              void* d_out, int out_size) {
    (void)in_sizes; (void)n_in; (void)out_size;
    const float* xd  = (const float*)d_in[0];
    const float* xm  = (const float*)d_in[1];
    const float* xt  = (const float*)d_in[2];
    const int*   xti = (const int*)d_in[3];
    const int*   yti = (const int*)d_in[4];

    const float* ug_w1 = (const float*)d_in[5];
    const float* ug_b1 = (const float*)d_in[6];
    const float* ug_w2 = (const float*)d_in[7];
    const float* ug_b2 = (const float*)d_in[8];
    const float* rg_w1 = (const float*)d_in[9];
    const float* rg_b1 = (const float*)d_in[10];
    const float* rg_w2 = (const float*)d_in[11];
    const float* rg_b2 = (const float*)d_in[12];
    const float* ns_w1 = (const float*)d_in[13];
    const float* ns_b1 = (const float*)d_in[14];
    const float* ns_w2 = (const float*)d_in[15];
    const float* ns_b2 = (const float*)d_in[16];
    const float* out_w1 = (const float*)d_in[17];
    const float* out_b1 = (const float*)d_in[18];
    const float* out_w2 = (const float*)d_in[19];
    const float* out_b2 = (const float*)d_in[20];
    const float* f_w1  = (const float*)d_in[21];
    const float* f_b1  = (const float*)d_in[22];
    const float* f_w2  = (const float*)d_in[23];
    const float* f_b2  = (const float*)d_in[24];

    // Unconditional (idempotent, non-stream API; no static guards allowed)
    cudaFuncSetAttribute(recur_kernel,
                         cudaFuncAttributeMaxDynamicSharedMemorySize,
                         SMEM_FLOATS * (int)sizeof(float));

    init_kernel<<<1, 256>>>(xt, xti, yti);
    conv_kernel<<<256, 256>>>(f_w1, f_w2, ug_w1, ug_w2, rg_w1, rg_w2,
                              ns_w1, ns_w2, out_w1);

    recur_kernel<<<GRID, NTHR, SMEM_FLOATS * sizeof(float)>>>(
        xd, xm,
        ug_b1, ug_b2, rg_b1, rg_b2, ns_b1, ns_b2,
        out_b1, out_w2, out_b2, f_b1, f_b2,
        (float*)d_out);
}